// round 11
// baseline (speedup 1.0000x reference)
#include <cuda_runtime.h>

// SIR RK4: B=65536 systems, params[b]=(beta,gamma,S0,I0), out[b][t][3], 199 steps.
//
// R8 kernel, third submission (two GB300 container/broker failures in a row; the
// source is structurally identical to the R5 kernel that ran clean, so the failures
// are attributed to infra flakiness, matching the R2 precedent).
//
// Config: 1 system/thread (2048 warps -> 3.46/SMSP, covers the store-stall exposure
// that capped R6/R7 at issue=44%), float4-batched stores (R5), SUBSTEPS=2.
// Truncation ladder measured from rel_err(S8)=7.64e-7 vs rel_err(S4)=7.91e-7:
// trunc(S4)~3e-8 -> trunc(S2)~5e-7 (h^4 scaling), ~2000x under the 1e-3 gate.

#define NUM_T    200
#define SUBSTEPS 2

struct Coef {
    float h2b, hb, c6b, h2g, hg, c6g;
};

__device__ __forceinline__ void rk4_step(float& S, float& I, const Coef& c)
{
#pragma unroll
    for (int s = 0; s < SUBSTEPS; ++s) {
        // stage 1 at (S, I)
        float u1  = S * I;
        float in1 = fmaf(-c.h2g, I, I);
        float S2  = fmaf(-c.h2b, u1, S);
        float I2  = fmaf( c.h2b, u1, in1);
        // stage 2 at (S2, I2)
        float u2  = S2 * I2;
        float in2 = fmaf(-c.h2g, I2, I);
        float S3  = fmaf(-c.h2b, u2, S);
        float I3  = fmaf( c.h2b, u2, in2);
        // stage 3 at (S3, I3), full step
        float u3  = S3 * I3;
        float in3 = fmaf(-c.hg, I3, I);
        float S4  = fmaf(-c.hb, u3, S);
        float I4  = fmaf( c.hb, u3, in3);
        // stage 4
        float u4  = S4 * I4;
        // weighted sums (off the critical path)
        float accU = fmaf(2.0f, u2, u1);
        accU       = fmaf(2.0f, u3, accU);
        accU       = accU + u4;
        float accI = fmaf(2.0f, I2, I);
        accI       = fmaf(2.0f, I3, accI);
        accI       = accI + I4;
        // combine
        S        = fmaf(-c.c6b, accU, S);
        float tI = fmaf( c.c6b, accU, I);
        I        = fmaf(-c.c6g, accI, tI);
    }
}

__global__ __launch_bounds__(64)
void sir_rk4_kernel(const float* __restrict__ params,
                    float* __restrict__ out,
                    int B)
{
    const int b = blockIdx.x * 64 + threadIdx.x;
    if (b >= B) return;

    const float4 p = reinterpret_cast<const float4*>(params)[b];
    float S = p.z;
    float I = p.w;

    const float DT = 100.0f / 199.0f;
    const float H  = DT / (float)SUBSTEPS;
    Coef c;
    c.h2b = 0.5f * H * p.x;
    c.hb  = H * p.x;
    c.c6b = (H / 6.0f) * p.x;
    c.h2g = 0.5f * H * p.y;
    c.hg  = H * p.y;
    c.c6g = (H / 6.0f) * p.y;

    float4* rowv = reinterpret_cast<float4*>(out + (size_t)b * (NUM_T * 3));

    // group 0: t=0 snapshot + 3 steps -> rowv[0..2]
    {
        float4 b0, b1, b2;
        b0.x = S; b0.y = I; b0.z = 1.0f - S - I;
        rk4_step(S, I, c);
        b0.w = S; b1.x = I; b1.y = 1.0f - S - I;
        rk4_step(S, I, c);
        b1.z = S; b1.w = I; b2.x = 1.0f - S - I;
        rk4_step(S, I, c);
        b2.y = S; b2.z = I; b2.w = 1.0f - S - I;
        rowv[0] = b0; rowv[1] = b1; rowv[2] = b2;
    }

    // groups 1..49: 4 steps each -> rowv[3g .. 3g+2]
    for (int g = 1; g < NUM_T / 4; ++g) {
        float4 b0, b1, b2;
        rk4_step(S, I, c);
        b0.x = S; b0.y = I; b0.z = 1.0f - S - I;
        rk4_step(S, I, c);
        b0.w = S; b1.x = I; b1.y = 1.0f - S - I;
        rk4_step(S, I, c);
        b1.z = S; b1.w = I; b2.x = 1.0f - S - I;
        rk4_step(S, I, c);
        b2.y = S; b2.z = I; b2.w = 1.0f - S - I;
        float4* o = rowv + g * 3;
        o[0] = b0; o[1] = b1; o[2] = b2;
    }
}

extern "C" void kernel_launch(void* const* d_in, const int* in_sizes, int n_in,
                              void* d_out, int out_size)
{
    const float* params = (const float*)d_in[0];
    float* out = (float*)d_out;
    const int B = in_sizes[0] / 4;          // 65536

    const int block = 64;
    const int grid = (B + block - 1) / block;   // 1024 blocks
    sir_rk4_kernel<<<grid, block>>>(params, out, B);
}

// round 12
// speedup vs baseline: 1.5625x; 1.5625x over previous
#include <cuda_runtime.h>

// SIR RK4: B=65536 systems, params[b]=(beta,gamma,S0,I0), out[b][t][3], 199 steps.
//
// R12: SMEM-staged coalesced stores. R8/R11 showed diverged STG (32 wavefronts per
// warp-store, ~66k L1 cycles/SM) is the exposed-latency wall once compute shrank.
// Each block (64 threads = 64 consecutive systems, rows contiguous in GMEM) stages
// 40 timesteps (120 floats/row, pitch 121 -> conflict-free) in SMEM, then flushes
// linearly: consecutive lanes write consecutive floats of a row -> full-line
// coalesced STG.32. GMEM store wavefronts drop 32x. SUBSTEPS=2 kept (rel_err
// 1.09e-6 measured, ~900x under the 1e-3 gate).

#define NUM_T    200
#define SUBSTEPS 2
#define WIN_T    40                 // timesteps staged per window (5 windows x 40 = 200)
#define ROW_F    (WIN_T * 3)        // 120 floats per row per window
#define PITCH    (ROW_F + 1)        // 121 floats: 121 mod 32 = 25 (odd) -> conflict-free
#define BLOCK    64

struct Coef {
    float h2b, hb, c6b, h2g, hg, c6g;
};

__device__ __forceinline__ void rk4_step(float& S, float& I, const Coef& c)
{
#pragma unroll
    for (int s = 0; s < SUBSTEPS; ++s) {
        // stage 1 at (S, I)
        float u1  = S * I;
        float in1 = fmaf(-c.h2g, I, I);
        float S2  = fmaf(-c.h2b, u1, S);
        float I2  = fmaf( c.h2b, u1, in1);
        // stage 2 at (S2, I2)
        float u2  = S2 * I2;
        float in2 = fmaf(-c.h2g, I2, I);
        float S3  = fmaf(-c.h2b, u2, S);
        float I3  = fmaf( c.h2b, u2, in2);
        // stage 3 at (S3, I3), full step
        float u3  = S3 * I3;
        float in3 = fmaf(-c.hg, I3, I);
        float S4  = fmaf(-c.hb, u3, S);
        float I4  = fmaf( c.hb, u3, in3);
        // stage 4
        float u4  = S4 * I4;
        // weighted sums (off the critical path)
        float accU = fmaf(2.0f, u2, u1);
        accU       = fmaf(2.0f, u3, accU);
        accU       = accU + u4;
        float accI = fmaf(2.0f, I2, I);
        accI       = fmaf(2.0f, I3, accI);
        accI       = accI + I4;
        // combine
        S        = fmaf(-c.c6b, accU, S);
        float tI = fmaf( c.c6b, accU, I);
        I        = fmaf(-c.c6g, accI, tI);
    }
}

__global__ __launch_bounds__(BLOCK)
void sir_rk4_kernel(const float* __restrict__ params,
                    float* __restrict__ out)
{
    __shared__ float stage[BLOCK * PITCH];      // 64 * 121 * 4 = 30,976 B

    const int tid = threadIdx.x;
    const int b   = blockIdx.x * BLOCK + tid;   // grid*block == B exactly

    const float4 p = reinterpret_cast<const float4*>(params)[b];
    float S = p.z;
    float I = p.w;

    const float DT = 100.0f / 199.0f;
    const float H  = DT / (float)SUBSTEPS;
    Coef c;
    c.h2b = 0.5f * H * p.x;
    c.hb  = H * p.x;
    c.c6b = (H / 6.0f) * p.x;
    c.h2g = 0.5f * H * p.y;
    c.hg  = H * p.y;
    c.c6g = (H / 6.0f) * p.y;

    // GMEM base of this block's 64 contiguous rows
    float* blk_out = out + (size_t)blockIdx.x * BLOCK * (NUM_T * 3);
    float* myrow   = &stage[tid * PITCH];

#pragma unroll 1
    for (int w = 0; w < NUM_T / WIN_T; ++w) {
        // ---- compute phase: fill my staged row ----
        int cc = 0;
        if (w == 0) {                            // t = 0 snapshot
            myrow[0] = S;
            myrow[1] = I;
            myrow[2] = 1.0f - S - I;
            cc = 3;
        }
        const int nsteps = (w == 0) ? (WIN_T - 1) : WIN_T;
#pragma unroll 1
        for (int s = 0; s < nsteps; ++s) {
            rk4_step(S, I, c);
            myrow[cc]     = S;
            myrow[cc + 1] = I;
            myrow[cc + 2] = 1.0f - S - I;
            cc += 3;
        }
        __syncthreads();

        // ---- flush phase: coalesced linear copy SMEM -> GMEM ----
        // element i -> row r = i/ROW_F, col = i%ROW_F
        // consecutive lanes -> consecutive cols of one row -> coalesced STG.32
        float* dst = blk_out + w * ROW_F;
#pragma unroll 1
        for (int i = tid; i < BLOCK * ROW_F; i += BLOCK) {
            int r  = i / ROW_F;
            int col = i - r * ROW_F;
            dst[r * (NUM_T * 3) + col] = stage[r * PITCH + col];
        }
        __syncthreads();
    }
}

extern "C" void kernel_launch(void* const* d_in, const int* in_sizes, int n_in,
                              void* d_out, int out_size)
{
    const float* params = (const float*)d_in[0];
    float* out = (float*)d_out;
    const int B = in_sizes[0] / 4;          // 65536

    const int grid = B / BLOCK;             // 1024 blocks, exact cover
    sir_rk4_kernel<<<grid, BLOCK>>>(params, out);
}

// round 13
// speedup vs baseline: 1.5810x; 1.0119x over previous
#include <cuda_runtime.h>

// SIR RK4: B=65536 systems, params[b]=(beta,gamma,S0,I0), out[b][t][3], 199 steps.
//
// R12: SMEM-staged coalesced stores. R8/R11 showed diverged STG (32 wavefronts per
// warp-store, ~66k L1 cycles/SM) is the exposed-latency wall once compute shrank.
// Each block (64 threads = 64 consecutive systems, rows contiguous in GMEM) stages
// 40 timesteps (120 floats/row, pitch 121 -> conflict-free) in SMEM, then flushes
// linearly: consecutive lanes write consecutive floats of a row -> full-line
// coalesced STG.32. GMEM store wavefronts drop 32x. SUBSTEPS=2 kept (rel_err
// 1.09e-6 measured, ~900x under the 1e-3 gate).

#define NUM_T    200
#define SUBSTEPS 2
#define WIN_T    40                 // timesteps staged per window (5 windows x 40 = 200)
#define ROW_F    (WIN_T * 3)        // 120 floats per row per window
#define PITCH    (ROW_F + 1)        // 121 floats: 121 mod 32 = 25 (odd) -> conflict-free
#define BLOCK    64

struct Coef {
    float h2b, hb, c6b, h2g, hg, c6g;
};

__device__ __forceinline__ void rk4_step(float& S, float& I, const Coef& c)
{
#pragma unroll
    for (int s = 0; s < SUBSTEPS; ++s) {
        // stage 1 at (S, I)
        float u1  = S * I;
        float in1 = fmaf(-c.h2g, I, I);
        float S2  = fmaf(-c.h2b, u1, S);
        float I2  = fmaf( c.h2b, u1, in1);
        // stage 2 at (S2, I2)
        float u2  = S2 * I2;
        float in2 = fmaf(-c.h2g, I2, I);
        float S3  = fmaf(-c.h2b, u2, S);
        float I3  = fmaf( c.h2b, u2, in2);
        // stage 3 at (S3, I3), full step
        float u3  = S3 * I3;
        float in3 = fmaf(-c.hg, I3, I);
        float S4  = fmaf(-c.hb, u3, S);
        float I4  = fmaf( c.hb, u3, in3);
        // stage 4
        float u4  = S4 * I4;
        // weighted sums (off the critical path)
        float accU = fmaf(2.0f, u2, u1);
        accU       = fmaf(2.0f, u3, accU);
        accU       = accU + u4;
        float accI = fmaf(2.0f, I2, I);
        accI       = fmaf(2.0f, I3, accI);
        accI       = accI + I4;
        // combine
        S        = fmaf(-c.c6b, accU, S);
        float tI = fmaf( c.c6b, accU, I);
        I        = fmaf(-c.c6g, accI, tI);
    }
}

__global__ __launch_bounds__(BLOCK)
void sir_rk4_kernel(const float* __restrict__ params,
                    float* __restrict__ out)
{
    __shared__ float stage[BLOCK * PITCH];      // 64 * 121 * 4 = 30,976 B

    const int tid = threadIdx.x;
    const int b   = blockIdx.x * BLOCK + tid;   // grid*block == B exactly

    const float4 p = reinterpret_cast<const float4*>(params)[b];
    float S = p.z;
    float I = p.w;

    const float DT = 100.0f / 199.0f;
    const float H  = DT / (float)SUBSTEPS;
    Coef c;
    c.h2b = 0.5f * H * p.x;
    c.hb  = H * p.x;
    c.c6b = (H / 6.0f) * p.x;
    c.h2g = 0.5f * H * p.y;
    c.hg  = H * p.y;
    c.c6g = (H / 6.0f) * p.y;

    // GMEM base of this block's 64 contiguous rows
    float* blk_out = out + (size_t)blockIdx.x * BLOCK * (NUM_T * 3);
    float* myrow   = &stage[tid * PITCH];

#pragma unroll 1
    for (int w = 0; w < NUM_T / WIN_T; ++w) {
        // ---- compute phase: fill my staged row ----
        int cc = 0;
        if (w == 0) {                            // t = 0 snapshot
            myrow[0] = S;
            myrow[1] = I;
            myrow[2] = 1.0f - S - I;
            cc = 3;
        }
        const int nsteps = (w == 0) ? (WIN_T - 1) : WIN_T;
#pragma unroll 1
        for (int s = 0; s < nsteps; ++s) {
            rk4_step(S, I, c);
            myrow[cc]     = S;
            myrow[cc + 1] = I;
            myrow[cc + 2] = 1.0f - S - I;
            cc += 3;
        }
        __syncthreads();

        // ---- flush phase: coalesced linear copy SMEM -> GMEM ----
        // element i -> row r = i/ROW_F, col = i%ROW_F
        // consecutive lanes -> consecutive cols of one row -> coalesced STG.32
        float* dst = blk_out + w * ROW_F;
#pragma unroll 1
        for (int i = tid; i < BLOCK * ROW_F; i += BLOCK) {
            int r  = i / ROW_F;
            int col = i - r * ROW_F;
            dst[r * (NUM_T * 3) + col] = stage[r * PITCH + col];
        }
        __syncthreads();
    }
}

extern "C" void kernel_launch(void* const* d_in, const int* in_sizes, int n_in,
                              void* d_out, int out_size)
{
    const float* params = (const float*)d_in[0];
    float* out = (float*)d_out;
    const int B = in_sizes[0] / 4;          // 65536

    const int grid = B / BLOCK;             // 1024 blocks, exact cover
    sir_rk4_kernel<<<grid, BLOCK>>>(params, out);
}